// round 6
// baseline (speedup 1.0000x reference)
#include <cuda_runtime.h>
#include <cuda_fp16.h>
#include <cstdint>

// ============================================================================
// out[n,c,hw] = sum_k g[(c-k)&255] * act[n,k,hw]   (circulant inverse GEMM)
// fp16 mma.sync m16n8k16 (fp32 accum), warp-specialized producer/consumer:
//   8 consumer warps (4M x 2N, 64c x 32hw each) : LDSM + MMA only
//   4 producer warps : LDG fp32 -> cvt fp16 -> STS, 8-stage one-shot mbarriers
// CTA: 256c x 64hw, 384 threads, 2 CTAs/SM. No __syncthreads in main loop.
// ============================================================================

__device__ __align__(16) __half aext_g[256 * 32];

// ---------------------------------------------------------------------------
// Prep: g = IDFT(1/DFT(delta - padded_rolled_ricker)); circulant fp16 table.
// ---------------------------------------------------------------------------
__global__ void prep_kernel(const float* __restrict__ filt) {
    __shared__ float m_s[256];
    __shared__ float twc[256];
    __shared__ float tws[256];
    __shared__ float gre[256];
    __shared__ float gim[256];
    __shared__ float g_s[256];

    int t = threadIdx.x;
    // pad_left = (256-27)/2 = 114 ; roll by 256/2+1 = 129
    int p = (t - 129) & 255;
    float kv = (p >= 114 && p < 141) ? filt[p - 114] : 0.0f;
    m_s[t] = (t == 0 ? 1.0f : 0.0f) - kv;

    float s, c;
    sincospif(-(float)t / 128.0f, &s, &c);
    twc[t] = c;
    tws[t] = s;
    __syncthreads();

    float re = 0.0f, im = 0.0f;
    for (int d = 0; d < 256; ++d) {
        int idx = (t * d) & 255;
        re = fmaf(m_s[d], twc[idx], re);
        im = fmaf(m_s[d], tws[idx], im);
    }
    float inv = 1.0f / (re * re + im * im);
    gre[t] = re * inv;
    gim[t] = -im * inv;
    __syncthreads();

    float g = 0.0f;
    for (int q = 0; q < 256; ++q) {
        int idx = (t * q) & 255;
        g = fmaf(gre[q], twc[idx], g);
        g = fmaf(gim[q], tws[idx], g);
    }
    g_s[t] = g * (1.0f / 256.0f);
    __syncthreads();

    for (int kk = 0; kk < 32; ++kk)
        aext_g[t * 32 + kk] = __float2half_rn(g_s[(t - kk) & 255]);
}

// ---------------------------------------------------------------------------
// PTX helpers (base PTX: ldmatrix/mma sm_80, mbarrier try_wait sm_90)
// ---------------------------------------------------------------------------
__device__ __forceinline__ uint32_t smem_u32(const void* p) {
    uint32_t a;
    asm("{ .reg .u64 t; cvta.to.shared.u64 t, %1; cvt.u32.u64 %0, t; }"
        : "=r"(a) : "l"(p));
    return a;
}
__device__ __forceinline__ void ldsm_x4(uint32_t* r, uint32_t addr) {
    asm volatile("ldmatrix.sync.aligned.m8n8.x4.shared.b16 {%0,%1,%2,%3}, [%4];"
                 : "=r"(r[0]), "=r"(r[1]), "=r"(r[2]), "=r"(r[3]) : "r"(addr));
}
__device__ __forceinline__ void ldsm_x4_t(uint32_t* r, uint32_t addr) {
    asm volatile("ldmatrix.sync.aligned.m8n8.x4.trans.shared.b16 {%0,%1,%2,%3}, [%4];"
                 : "=r"(r[0]), "=r"(r[1]), "=r"(r[2]), "=r"(r[3]) : "r"(addr));
}
__device__ __forceinline__ void mma16816(float* d, const uint32_t* a,
                                         const uint32_t* b) {
    asm volatile(
        "mma.sync.aligned.m16n8k16.row.col.f32.f16.f16.f32 "
        "{%0,%1,%2,%3},{%4,%5,%6,%7},{%8,%9},{%0,%1,%2,%3};"
        : "+f"(d[0]), "+f"(d[1]), "+f"(d[2]), "+f"(d[3])
        : "r"(a[0]), "r"(a[1]), "r"(a[2]), "r"(a[3]), "r"(b[0]), "r"(b[1]));
}
__device__ __forceinline__ void mbar_init(uint32_t a, uint32_t cnt) {
    asm volatile("mbarrier.init.shared.b64 [%0], %1;" :: "r"(a), "r"(cnt) : "memory");
}
__device__ __forceinline__ void mbar_arrive(uint32_t a) {
    asm volatile("mbarrier.arrive.shared.b64 _, [%0];" :: "r"(a) : "memory");
}
__device__ __forceinline__ void mbar_wait0(uint32_t a) {
    uint32_t done = 0;
    while (!done) {
        asm volatile(
            "{ .reg .pred p; mbarrier.try_wait.parity.acquire.cta.shared::cta.b64 "
            "p, [%1], 0, 0x989680; selp.b32 %0,1,0,p; }"
            : "=r"(done) : "r"(a) : "memory");
    }
}

// SMEM layout
static constexpr uint32_t A_PITCH = 80;    // 32 fp16 (64B) + 16B pad
static constexpr uint32_t B_PITCH = 144;   // 64 fp16 (128B) + 16B pad
static constexpr uint32_t OFF_A   = 0;                 // 256*80 = 20480
static constexpr uint32_t OFF_BAR = 20480;             // 8 x 8B mbarriers
static constexpr uint32_t OFF_B   = 20544;
static constexpr uint32_t B_STG   = 32 * B_PITCH;      // 4608
static constexpr uint32_t SMEM_BYTES = 20544 + 8 * B_STG;  // 57408

__global__ __launch_bounds__(384, 2)
void mma_toeplitz_kernel(const float* __restrict__ act, float* __restrict__ out) {
    extern __shared__ __align__(128) char smem[];
    const uint32_t sb = smem_u32(smem);
    const int tid = threadIdx.x;
    const int lid = tid & 31;
    const int wid = tid >> 5;
    const int hw0 = blockIdx.x * 64;
    const int n   = blockIdx.y;

    const float* actn = act + (size_t)n * (256 * 4096);
    float*       outn = out + (size_t)n * (256 * 4096);

    if (tid == 0) {
#pragma unroll
        for (int s = 0; s < 8; ++s) mbar_init(sb + OFF_BAR + s * 8, 128);
    }
    // Copy circulant A table gmem -> smem (64B rows -> pitch 80)
    {
        const float4* src = (const float4*)aext_g;
        for (int i = tid; i < 1024; i += 384) {
            uint32_t dst = (uint32_t)(i >> 2) * A_PITCH + (uint32_t)(i & 3) * 16;
            *(float4*)(smem + OFF_A + dst) = src[i];
        }
    }
    __syncthreads();

    if (wid >= 8) {
        // ---------------- Producer: 4 warps, 128 threads -------------------
        const int pt = tid - 256;     // 0..127
        float4 buf[2][4];

        // prologue: chunks 0 and 1 in flight
#pragma unroll
        for (int i = 0; i < 4; ++i) {
            int f = pt + i * 128;     // 0..511
            buf[0][i] = *(const float4*)&actn[(size_t)(f >> 4) * 4096 + hw0 + (f & 15) * 4];
        }
#pragma unroll
        for (int i = 0; i < 4; ++i) {
            int f = pt + i * 128;
            buf[1][i] = *(const float4*)&actn[(size_t)(32 + (f >> 4)) * 4096 + hw0 + (f & 15) * 4];
        }

#pragma unroll
        for (int j = 0; j < 8; ++j) {
            float4* cur = buf[j & 1];
            // issue next LDGs first (overlap with STS)
            float4 nxt[4];
            if (j < 6) {
#pragma unroll
                for (int i = 0; i < 4; ++i) {
                    int f = pt + i * 128;
                    nxt[i] = *(const float4*)&actn[(size_t)((j + 2) * 32 + (f >> 4)) * 4096 + hw0 + (f & 15) * 4];
                }
            }
            // convert + STS chunk j
            char* stg = smem + OFF_B + (uint32_t)j * B_STG;
#pragma unroll
            for (int i = 0; i < 4; ++i) {
                int f = pt + i * 128;
                __half2 a = __floats2half2_rn(cur[i].x, cur[i].y);
                __half2 b = __floats2half2_rn(cur[i].z, cur[i].w);
                *(uint2*)(stg + (uint32_t)(f >> 4) * B_PITCH + (uint32_t)(f & 15) * 8) =
                    make_uint2(*(uint32_t*)&a, *(uint32_t*)&b);
            }
            mbar_arrive(sb + OFF_BAR + j * 8);
            if (j < 6) {
#pragma unroll
                for (int i = 0; i < 4; ++i) buf[j & 1][i] = nxt[i];
            }
        }
        return;
    }

    // ------------------ Consumer: 8 warps (4M x 2N) ------------------------
    const int warp_m = wid >> 1;   // 0..3 -> 64 c each
    const int warp_n = wid & 1;    // 0..1 -> 32 hw each

    float acc[4][4][4] = {};

    for (int j = 0; j < 8; ++j) {
        mbar_wait0(sb + OFF_BAR + j * 8);
        const uint32_t bbase = sb + OFF_B + (uint32_t)j * B_STG;
#pragma unroll
        for (int step = 0; step < 2; ++step) {
            uint32_t brow = (uint32_t)(step * 16 + (lid & 15));
            uint32_t Bf[2][4];
#pragma unroll
            for (int bh = 0; bh < 2; ++bh) {
                uint32_t bcol = (uint32_t)(warp_n * 32 + bh * 16 + ((lid >> 4) << 3));
                ldsm_x4_t(Bf[bh], bbase + brow * B_PITCH + bcol * 2);
            }
#pragma unroll
            for (int mt = 0; mt < 4; ++mt) {
                int sbase = ((warp_m * 64 + mt * 16) - j * 32) & 255;
                uint32_t arow = (uint32_t)(sbase + (lid & 15));
                uint32_t acol = (uint32_t)(step * 32 + ((lid >> 4) << 4));  // bytes
                uint32_t Af[4];
                ldsm_x4(Af, sb + OFF_A + arow * A_PITCH + acol);
                mma16816(acc[mt][0], Af, Bf[0]);
                mma16816(acc[mt][1], Af, Bf[0] + 2);
                mma16816(acc[mt][2], Af, Bf[1]);
                mma16816(acc[mt][3], Af, Bf[1] + 2);
            }
        }
    }

    // Epilogue: direct stores (lane quads cover 32B sectors)
#pragma unroll
    for (int mt = 0; mt < 4; ++mt) {
        int c = warp_m * 64 + mt * 16 + (lid >> 2);
#pragma unroll
        for (int nq = 0; nq < 4; ++nq) {
            int col = hw0 + warp_n * 32 + nq * 8 + (lid & 3) * 2;
            *(float2*)&outn[(size_t)c * 4096 + col] =
                make_float2(acc[mt][nq][0], acc[mt][nq][1]);
            *(float2*)&outn[(size_t)(c + 8) * 4096 + col] =
                make_float2(acc[mt][nq][2], acc[mt][nq][3]);
        }
    }
}

// ---------------------------------------------------------------------------
extern "C" void kernel_launch(void* const* d_in, const int* in_sizes, int n_in,
                              void* d_out, int out_size) {
    const float* act;
    const float* filt;
    if (n_in >= 2 && in_sizes[0] == 27) {
        filt = (const float*)d_in[0];
        act  = (const float*)d_in[1];
    } else {
        act  = (const float*)d_in[0];
        filt = (const float*)d_in[1];
    }

    cudaFuncSetAttribute(mma_toeplitz_kernel,
                         cudaFuncAttributeMaxDynamicSharedMemorySize, SMEM_BYTES);

    prep_kernel<<<1, 256>>>(filt);

    dim3 grid(4096 / 64, 32);   // (64, 32) = 2048 CTAs
    mma_toeplitz_kernel<<<grid, 384, SMEM_BYTES>>>(act, (float*)d_out);
}

// round 7
// speedup vs baseline: 1.4446x; 1.4446x over previous
#include <cuda_runtime.h>
#include <cuda_fp16.h>
#include <cstdint>

// ============================================================================
// out[n,c,hw] = sum_k g[(c-k)&255] * act[n,k,hw]   (circulant inverse GEMM)
// fp16 mma.sync m16n8k16 (fp32 accum). cp.async 4-slot fp32 ring (3 deep),
// self-consistent per-thread copy->convert (no extra syncs). 1 sync/chunk.
// CTA: 256c x 64hw, 256 threads (8 warps = 4M x 2N), 2 CTAs/SM.
// ============================================================================

__device__ __align__(16) __half aext_g[256 * 32];

// ---------------------------------------------------------------------------
// Prep: g = IDFT(1/DFT(delta - padded_rolled_ricker)); circulant fp16 table.
// ---------------------------------------------------------------------------
__global__ void prep_kernel(const float* __restrict__ filt) {
    __shared__ float m_s[256];
    __shared__ float twc[256];
    __shared__ float tws[256];
    __shared__ float gre[256];
    __shared__ float gim[256];
    __shared__ float g_s[256];

    int t = threadIdx.x;
    // pad_left = (256-27)/2 = 114 ; roll by 256/2+1 = 129
    int p = (t - 129) & 255;
    float kv = (p >= 114 && p < 141) ? filt[p - 114] : 0.0f;
    m_s[t] = (t == 0 ? 1.0f : 0.0f) - kv;

    float s, c;
    sincospif(-(float)t / 128.0f, &s, &c);
    twc[t] = c;
    tws[t] = s;
    __syncthreads();

    float re = 0.0f, im = 0.0f;
    for (int d = 0; d < 256; ++d) {
        int idx = (t * d) & 255;
        re = fmaf(m_s[d], twc[idx], re);
        im = fmaf(m_s[d], tws[idx], im);
    }
    float inv = 1.0f / (re * re + im * im);
    gre[t] = re * inv;
    gim[t] = -im * inv;
    __syncthreads();

    float g = 0.0f;
    for (int q = 0; q < 256; ++q) {
        int idx = (t * q) & 255;
        g = fmaf(gre[q], twc[idx], g);
        g = fmaf(gim[q], tws[idx], g);
    }
    g_s[t] = g * (1.0f / 256.0f);
    __syncthreads();

    for (int kk = 0; kk < 32; ++kk)
        aext_g[t * 32 + kk] = __float2half_rn(g_s[(t - kk) & 255]);
}

// ---------------------------------------------------------------------------
// PTX helpers (base PTX: ldmatrix/mma/cp.async are sm_80 features)
// ---------------------------------------------------------------------------
__device__ __forceinline__ uint32_t smem_u32(const void* p) {
    uint32_t a;
    asm("{ .reg .u64 t; cvta.to.shared.u64 t, %1; cvt.u32.u64 %0, t; }"
        : "=r"(a) : "l"(p));
    return a;
}
__device__ __forceinline__ void ldsm_x4(uint32_t* r, uint32_t addr) {
    asm volatile("ldmatrix.sync.aligned.m8n8.x4.shared.b16 {%0,%1,%2,%3}, [%4];"
                 : "=r"(r[0]), "=r"(r[1]), "=r"(r[2]), "=r"(r[3]) : "r"(addr));
}
__device__ __forceinline__ void ldsm_x4_t(uint32_t* r, uint32_t addr) {
    asm volatile("ldmatrix.sync.aligned.m8n8.x4.trans.shared.b16 {%0,%1,%2,%3}, [%4];"
                 : "=r"(r[0]), "=r"(r[1]), "=r"(r[2]), "=r"(r[3]) : "r"(addr));
}
__device__ __forceinline__ void mma16816(float* d, const uint32_t* a,
                                         const uint32_t* b) {
    asm volatile(
        "mma.sync.aligned.m16n8k16.row.col.f32.f16.f16.f32 "
        "{%0,%1,%2,%3},{%4,%5,%6,%7},{%8,%9},{%0,%1,%2,%3};"
        : "+f"(d[0]), "+f"(d[1]), "+f"(d[2]), "+f"(d[3])
        : "r"(a[0]), "r"(a[1]), "r"(a[2]), "r"(a[3]), "r"(b[0]), "r"(b[1]));
}
__device__ __forceinline__ void cp_async16(uint32_t dst, const void* src) {
    asm volatile("cp.async.cg.shared.global [%0], [%1], 16;"
                 :: "r"(dst), "l"(src) : "memory");
}
__device__ __forceinline__ void cp_commit() {
    asm volatile("cp.async.commit_group;" ::: "memory");
}
template <int N>
__device__ __forceinline__ void cp_wait() {
    asm volatile("cp.async.wait_group %0;" :: "n"(N) : "memory");
}

// SMEM layout
static constexpr uint32_t A_PITCH = 80;    // 32 fp16 (64B) + 16B pad
static constexpr uint32_t S_PITCH = 272;   // 64 fp32 (256B) + 16B pad
static constexpr uint32_t B_PITCH = 144;   // 64 fp16 (128B) + 16B pad
static constexpr uint32_t OFF_A   = 0;                  // 256*80 = 20480
static constexpr uint32_t OFF_S   = 20480;              // fp32 ring, 4 slots
static constexpr uint32_t S_STG   = 32 * S_PITCH;       // 8704
static constexpr uint32_t OFF_B   = 20480 + 4 * S_STG;  // 55296, fp16 x2
static constexpr uint32_t B_STG   = 32 * B_PITCH;       // 4608
static constexpr uint32_t SMEM_BYTES = OFF_B + 2 * B_STG;  // 64512

__global__ __launch_bounds__(256, 2)
void mma_toeplitz_kernel(const float* __restrict__ act, float* __restrict__ out) {
    extern __shared__ __align__(128) char smem[];
    const uint32_t sb = smem_u32(smem);
    const int tid = threadIdx.x;
    const int lid = tid & 31;
    const int wid = tid >> 5;
    const int warp_m = wid >> 1;   // 0..3 -> 64 c each
    const int warp_n = wid & 1;    // 0..1 -> 32 hw each
    const int hw0 = blockIdx.x * 64;
    const int n   = blockIdx.y;

    const float* actn = act + (size_t)n * (256 * 4096);
    float*       outn = out + (size_t)n * (256 * 4096);

    // Copy circulant A table gmem -> smem (64B rows -> pitch 80)
    {
        const float4* src = (const float4*)aext_g;
#pragma unroll
        for (int l = 0; l < 4; ++l) {
            int i = tid + l * 256;
            uint32_t dst = (uint32_t)(i >> 2) * A_PITCH + (uint32_t)(i & 3) * 16;
            *(float4*)(smem + OFF_A + dst) = src[i];
        }
    }

    // Per-thread copy/convert coordinates (self-consistent: each thread
    // cp.asyncs exactly the 32 bytes it later converts -> no cross-thread
    // visibility needed between wait_group and the LDS).
    const int cr = tid >> 3;                         // k row 0..31
    const int cc = tid & 7;                          // 16B col 0..7
    const uint32_t ring_rd = (uint32_t)cr * S_PITCH + (uint32_t)cc * 16;
    const uint32_t sts_off = (uint32_t)cr * B_PITCH + (uint32_t)cc * 8;
    const float* gsrc = &actn[(size_t)cr * 4096 + hw0 + cc * 4];

#define CP_CHUNK(q)                                                          \
    do {                                                                     \
        uint32_t d0 = sb + OFF_S + (uint32_t)((q) & 3) * S_STG + ring_rd;    \
        const float* s0 = gsrc + (size_t)(q) * 32 * 4096;                    \
        cp_async16(d0, s0);                                                  \
        cp_async16(d0 + 128, s0 + 32);                                       \
        cp_commit();                                                         \
    } while (0)

#define CVT_CHUNK(q)                                                         \
    do {                                                                     \
        const char* slot = smem + OFF_S + (uint32_t)((q) & 3) * S_STG;       \
        float4 va = *(const float4*)(slot + ring_rd);                        \
        float4 vb = *(const float4*)(slot + ring_rd + 128);                  \
        char* bdst = smem + OFF_B + (uint32_t)((q) & 1) * B_STG;             \
        __half2 a0 = __floats2half2_rn(va.x, va.y);                          \
        __half2 a1 = __floats2half2_rn(va.z, va.w);                          \
        __half2 b0 = __floats2half2_rn(vb.x, vb.y);                          \
        __half2 b1 = __floats2half2_rn(vb.z, vb.w);                          \
        *(uint2*)(bdst + sts_off) =                                          \
            make_uint2(*(uint32_t*)&a0, *(uint32_t*)&a1);                    \
        *(uint2*)(bdst + sts_off + 64) =                                     \
            make_uint2(*(uint32_t*)&b0, *(uint32_t*)&b1);                    \
    } while (0)

    // Prologue: 3 chunks in flight, chunk 0 converted.
    CP_CHUNK(0);
    CP_CHUNK(1);
    CP_CHUNK(2);
    cp_wait<2>();
    CVT_CHUNK(0);

    float acc[4][4][4] = {};

#pragma unroll
    for (int j = 0; j < 8; ++j) {
        __syncthreads();  // fp16 buf(j&1) published; prev reads of buf done

        if (j + 3 < 8) CP_CHUNK(j + 3);

        const uint32_t bbase = sb + OFF_B + (uint32_t)(j & 1) * B_STG;
#pragma unroll
        for (int step = 0; step < 2; ++step) {
            uint32_t brow = (uint32_t)(step * 16 + (lid & 15));
            uint32_t Bf[2][4];
#pragma unroll
            for (int bh = 0; bh < 2; ++bh) {
                uint32_t bcol = (uint32_t)(warp_n * 32 + bh * 16 + ((lid >> 4) << 3));
                ldsm_x4_t(Bf[bh], bbase + brow * B_PITCH + bcol * 2);
            }
#pragma unroll
            for (int mt = 0; mt < 4; ++mt) {
                int sbase = ((warp_m * 64 + mt * 16) - j * 32) & 255;
                uint32_t arow = (uint32_t)(sbase + (lid & 15));
                uint32_t acol = (uint32_t)(step * 32 + ((lid >> 4) << 4));
                uint32_t Af[4];
                ldsm_x4(Af, sb + OFF_A + arow * A_PITCH + acol);
                mma16816(acc[mt][0], Af, Bf[0]);
                mma16816(acc[mt][1], Af, Bf[0] + 2);
                mma16816(acc[mt][2], Af, Bf[1]);
                mma16816(acc[mt][3], Af, Bf[1] + 2);
            }
        }

        // Convert chunk j+1 into the other fp16 buffer (own bytes only).
        if (j < 7) {
            if (j < 5)      cp_wait<2>();
            else if (j == 5) cp_wait<1>();
            else             cp_wait<0>();
            CVT_CHUNK(j + 1);
        }
    }
#undef CP_CHUNK
#undef CVT_CHUNK

    // Epilogue: direct stores (lane quads cover 32B sectors)
#pragma unroll
    for (int mt = 0; mt < 4; ++mt) {
        int c = warp_m * 64 + mt * 16 + (lid >> 2);
#pragma unroll
        for (int nq = 0; nq < 4; ++nq) {
            int col = hw0 + warp_n * 32 + nq * 8 + (lid & 3) * 2;
            *(float2*)&outn[(size_t)c * 4096 + col] =
                make_float2(acc[mt][nq][0], acc[mt][nq][1]);
            *(float2*)&outn[(size_t)(c + 8) * 4096 + col] =
                make_float2(acc[mt][nq][2], acc[mt][nq][3]);
        }
    }
}

// ---------------------------------------------------------------------------
extern "C" void kernel_launch(void* const* d_in, const int* in_sizes, int n_in,
                              void* d_out, int out_size) {
    const float* act;
    const float* filt;
    if (n_in >= 2 && in_sizes[0] == 27) {
        filt = (const float*)d_in[0];
        act  = (const float*)d_in[1];
    } else {
        act  = (const float*)d_in[0];
        filt = (const float*)d_in[1];
    }

    cudaFuncSetAttribute(mma_toeplitz_kernel,
                         cudaFuncAttributeMaxDynamicSharedMemorySize, SMEM_BYTES);

    prep_kernel<<<1, 256>>>(filt);

    dim3 grid(4096 / 64, 32);   // (64, 32) = 2048 CTAs
    mma_toeplitz_kernel<<<grid, 256, SMEM_BYTES>>>(act, (float*)d_out);
}

// round 8
// speedup vs baseline: 1.4458x; 1.0008x over previous
#include <cuda_runtime.h>
#include <cuda_fp16.h>
#include <cstdint>

// ============================================================================
// out[n,c,hw] = sum_k g[(c-k)&255] * act[n,k,hw]   (circulant inverse GEMM)
// fp16 mma.sync m16n8k16 (fp32 accum). Two independent 4-warp groups per CTA
// (disjoint 32-hw halves), each with its own cp.async fp32 ring + fp16 double
// buffer + named barrier (bar.sync 1+g). No CTA-wide sync in the main loop.
// CTA: 256c x 64hw, 256 threads, 2 CTAs/SM.
// ============================================================================

__device__ __align__(16) __half aext_g[256 * 32];

// ---------------------------------------------------------------------------
// Prep: g = IDFT(1/DFT(delta - padded_rolled_ricker)); circulant fp16 table.
// ---------------------------------------------------------------------------
__global__ void prep_kernel(const float* __restrict__ filt) {
    __shared__ float m_s[256];
    __shared__ float twc[256];
    __shared__ float tws[256];
    __shared__ float gre[256];
    __shared__ float gim[256];
    __shared__ float g_s[256];

    int t = threadIdx.x;
    // pad_left = (256-27)/2 = 114 ; roll by 256/2+1 = 129
    int p = (t - 129) & 255;
    float kv = (p >= 114 && p < 141) ? filt[p - 114] : 0.0f;
    m_s[t] = (t == 0 ? 1.0f : 0.0f) - kv;

    float s, c;
    sincospif(-(float)t / 128.0f, &s, &c);
    twc[t] = c;
    tws[t] = s;
    __syncthreads();

    float re = 0.0f, im = 0.0f;
    for (int d = 0; d < 256; ++d) {
        int idx = (t * d) & 255;
        re = fmaf(m_s[d], twc[idx], re);
        im = fmaf(m_s[d], tws[idx], im);
    }
    float inv = 1.0f / (re * re + im * im);
    gre[t] = re * inv;
    gim[t] = -im * inv;
    __syncthreads();

    float g = 0.0f;
    for (int q = 0; q < 256; ++q) {
        int idx = (t * q) & 255;
        g = fmaf(gre[q], twc[idx], g);
        g = fmaf(gim[q], tws[idx], g);
    }
    g_s[t] = g * (1.0f / 256.0f);
    __syncthreads();

    for (int kk = 0; kk < 32; ++kk)
        aext_g[t * 32 + kk] = __float2half_rn(g_s[(t - kk) & 255]);
}

// ---------------------------------------------------------------------------
// PTX helpers (base PTX: ldmatrix/mma/cp.async sm_80; named bar.sync sm_70)
// ---------------------------------------------------------------------------
__device__ __forceinline__ uint32_t smem_u32(const void* p) {
    uint32_t a;
    asm("{ .reg .u64 t; cvta.to.shared.u64 t, %1; cvt.u32.u64 %0, t; }"
        : "=r"(a) : "l"(p));
    return a;
}
__device__ __forceinline__ void ldsm_x4(uint32_t* r, uint32_t addr) {
    asm volatile("ldmatrix.sync.aligned.m8n8.x4.shared.b16 {%0,%1,%2,%3}, [%4];"
                 : "=r"(r[0]), "=r"(r[1]), "=r"(r[2]), "=r"(r[3]) : "r"(addr));
}
__device__ __forceinline__ void ldsm_x4_t(uint32_t* r, uint32_t addr) {
    asm volatile("ldmatrix.sync.aligned.m8n8.x4.trans.shared.b16 {%0,%1,%2,%3}, [%4];"
                 : "=r"(r[0]), "=r"(r[1]), "=r"(r[2]), "=r"(r[3]) : "r"(addr));
}
__device__ __forceinline__ void mma16816(float* d, const uint32_t* a,
                                         const uint32_t* b) {
    asm volatile(
        "mma.sync.aligned.m16n8k16.row.col.f32.f16.f16.f32 "
        "{%0,%1,%2,%3},{%4,%5,%6,%7},{%8,%9},{%0,%1,%2,%3};"
        : "+f"(d[0]), "+f"(d[1]), "+f"(d[2]), "+f"(d[3])
        : "r"(a[0]), "r"(a[1]), "r"(a[2]), "r"(a[3]), "r"(b[0]), "r"(b[1]));
}
__device__ __forceinline__ void cp_async16(uint32_t dst, const void* src) {
    asm volatile("cp.async.cg.shared.global [%0], [%1], 16;"
                 :: "r"(dst), "l"(src) : "memory");
}
__device__ __forceinline__ void cp_commit() {
    asm volatile("cp.async.commit_group;" ::: "memory");
}
template <int N>
__device__ __forceinline__ void cp_wait() {
    asm volatile("cp.async.wait_group %0;" :: "n"(N) : "memory");
}
__device__ __forceinline__ void bar_group(int id) {
    asm volatile("bar.sync %0, 128;" :: "r"(id) : "memory");
}

// SMEM layout
static constexpr uint32_t A_PITCH = 80;    // 32 fp16 (64B) + 16B pad
static constexpr uint32_t S_PITCH = 144;   // 32 fp32 (128B) + 16B pad
static constexpr uint32_t B_PITCH = 80;    // 32 fp16 (64B) + 16B pad
static constexpr uint32_t OFF_A   = 0;                    // 256*80 = 20480
static constexpr uint32_t OFF_S   = 20480;                // fp32 rings
static constexpr uint32_t S_SLOT  = 32 * S_PITCH;         // 4608
static constexpr uint32_t S_GRP   = 4 * S_SLOT;           // 18432 per group
static constexpr uint32_t OFF_B   = 20480 + 2 * S_GRP;    // 57344
static constexpr uint32_t B_BUF   = 32 * B_PITCH;         // 2560
static constexpr uint32_t B_GRP   = 2 * B_BUF;            // 5120 per group
static constexpr uint32_t SMEM_BYTES = OFF_B + 2 * B_GRP; // 67584

__global__ __launch_bounds__(256, 2)
void mma_toeplitz_kernel(const float* __restrict__ act, float* __restrict__ out) {
    extern __shared__ __align__(128) char smem[];
    const uint32_t sb = smem_u32(smem);
    const int tid = threadIdx.x;
    const int lid = tid & 31;
    const int wid = tid >> 5;
    const int warp_m = wid >> 1;   // 0..3 -> 64 c each
    const int g      = wid & 1;    // group: 32-hw half
    const int hw0 = blockIdx.x * 64;
    const int n   = blockIdx.y;

    const float* actn = act + (size_t)n * (256 * 4096);
    float*       outn = out + (size_t)n * (256 * 4096);

    // Copy circulant A table gmem -> smem (64B rows -> pitch 80)
    {
        const float4* src = (const float4*)aext_g;
#pragma unroll
        for (int l = 0; l < 4; ++l) {
            int i = tid + l * 256;
            uint32_t dst = (uint32_t)(i >> 2) * A_PITCH + (uint32_t)(i & 3) * 16;
            *(float4*)(smem + OFF_A + dst) = src[i];
        }
    }

    // Per-thread copy/convert coordinates within the group (self-consistent:
    // each thread cp.asyncs exactly the 32B it later converts).
    const int gt = ((wid >> 1) << 5) | lid;  // 0..127 within group
    const int cr = gt >> 2;                  // k row 0..31
    const int cc = gt & 3;                   // 32B col 0..3
    const uint32_t ring_rd = sb + OFF_S + (uint32_t)g * S_GRP +
                             (uint32_t)cr * S_PITCH + (uint32_t)cc * 32;
    const uint32_t bgrp    = sb + OFF_B + (uint32_t)g * B_GRP;
    const uint32_t sts_off = (uint32_t)cr * B_PITCH + (uint32_t)cc * 16;
    const float* gsrc = &actn[(size_t)cr * 4096 + hw0 + g * 32 + cc * 8];
    const int bar_id = 1 + g;

#define CP_CHUNK(q)                                                          \
    do {                                                                     \
        uint32_t d0 = ring_rd + (uint32_t)((q) & 3) * S_SLOT;                \
        const float* s0 = gsrc + (size_t)(q) * 32 * 4096;                    \
        cp_async16(d0, s0);                                                  \
        cp_async16(d0 + 16, s0 + 4);                                         \
        cp_commit();                                                         \
    } while (0)

#define CVT_CHUNK(q)                                                         \
    do {                                                                     \
        uint32_t s0 = ring_rd + (uint32_t)((q) & 3) * S_SLOT;                \
        float4 va, vb;                                                       \
        asm volatile("ld.shared.v4.f32 {%0,%1,%2,%3}, [%4];"                 \
                     : "=f"(va.x), "=f"(va.y), "=f"(va.z), "=f"(va.w)        \
                     : "r"(s0));                                             \
        asm volatile("ld.shared.v4.f32 {%0,%1,%2,%3}, [%4];"                 \
                     : "=f"(vb.x), "=f"(vb.y), "=f"(vb.z), "=f"(vb.w)        \
                     : "r"(s0 + 16));                                        \
        __half2 a0 = __floats2half2_rn(va.x, va.y);                          \
        __half2 a1 = __floats2half2_rn(va.z, va.w);                          \
        __half2 b0 = __floats2half2_rn(vb.x, vb.y);                          \
        __half2 b1 = __floats2half2_rn(vb.z, vb.w);                          \
        uint32_t d0 = bgrp + (uint32_t)((q) & 1) * B_BUF + sts_off;          \
        asm volatile("st.shared.v4.b32 [%0], {%1,%2,%3,%4};"                 \
                     :: "r"(d0), "r"(*(uint32_t*)&a0), "r"(*(uint32_t*)&a1), \
                        "r"(*(uint32_t*)&b0), "r"(*(uint32_t*)&b1)           \
                     : "memory");                                            \
    } while (0)

    __syncthreads();   // A table visible to all

    // Prologue: 3 chunks in flight, chunk 0 converted (own bytes only).
    CP_CHUNK(0);
    CP_CHUNK(1);
    CP_CHUNK(2);
    cp_wait<2>();
    CVT_CHUNK(0);

    float acc[4][4][4] = {};

#pragma unroll
    for (int j = 0; j < 8; ++j) {
        bar_group(bar_id);  // group's STS(j) published; prior reads of buf done

        if (j + 3 < 8) CP_CHUNK(j + 3);

        const uint32_t bbase = bgrp + (uint32_t)(j & 1) * B_BUF;
#pragma unroll
        for (int step = 0; step < 2; ++step) {
            uint32_t brow = (uint32_t)(step * 16 + (lid & 15));
            uint32_t Bf[2][4];
#pragma unroll
            for (int bh = 0; bh < 2; ++bh) {
                uint32_t bcol = (uint32_t)(bh * 16 + ((lid >> 4) << 3));
                ldsm_x4_t(Bf[bh], bbase + brow * B_PITCH + bcol * 2);
            }
#pragma unroll
            for (int mt = 0; mt < 4; ++mt) {
                int sbase = ((warp_m * 64 + mt * 16) - j * 32) & 255;
                uint32_t arow = (uint32_t)(sbase + (lid & 15));
                uint32_t acol = (uint32_t)(step * 32 + ((lid >> 4) << 4));
                uint32_t Af[4];
                ldsm_x4(Af, sb + OFF_A + arow * A_PITCH + acol);
                mma16816(acc[mt][0], Af, Bf[0]);
                mma16816(acc[mt][1], Af, Bf[0] + 2);
                mma16816(acc[mt][2], Af, Bf[1]);
                mma16816(acc[mt][3], Af, Bf[1] + 2);
            }
        }

        // Convert chunk j+1 into the group's other fp16 buffer (own bytes).
        if (j < 7) {
            if (j < 5)       cp_wait<2>();
            else if (j == 5) cp_wait<1>();
            else             cp_wait<0>();
            CVT_CHUNK(j + 1);
        }
    }
#undef CP_CHUNK
#undef CVT_CHUNK

    // Epilogue: direct stores (lane quads cover 32B sectors)
#pragma unroll
    for (int mt = 0; mt < 4; ++mt) {
        int c = warp_m * 64 + mt * 16 + (lid >> 2);
#pragma unroll
        for (int nq = 0; nq < 4; ++nq) {
            int col = hw0 + g * 32 + nq * 8 + (lid & 3) * 2;
            *(float2*)&outn[(size_t)c * 4096 + col] =
                make_float2(acc[mt][nq][0], acc[mt][nq][1]);
            *(float2*)&outn[(size_t)(c + 8) * 4096 + col] =
                make_float2(acc[mt][nq][2], acc[mt][nq][3]);
        }
    }
}

// ---------------------------------------------------------------------------
extern "C" void kernel_launch(void* const* d_in, const int* in_sizes, int n_in,
                              void* d_out, int out_size) {
    const float* act;
    const float* filt;
    if (n_in >= 2 && in_sizes[0] == 27) {
        filt = (const float*)d_in[0];
        act  = (const float*)d_in[1];
    } else {
        act  = (const float*)d_in[0];
        filt = (const float*)d_in[1];
    }

    cudaFuncSetAttribute(mma_toeplitz_kernel,
                         cudaFuncAttributeMaxDynamicSharedMemorySize, SMEM_BYTES);

    prep_kernel<<<1, 256>>>(filt);

    dim3 grid(4096 / 64, 32);   // (64, 32) = 2048 CTAs
    mma_toeplitz_kernel<<<grid, 256, SMEM_BYTES>>>(act, (float*)d_out);
}